// round 13
// baseline (speedup 1.0000x reference)
#include <cuda_runtime.h>
#include <math_constants.h>
#include <math.h>

#define E 4
#define L 8
#define S 512
#define F 32
#define SAMPLE 512
#define ELF (E * L * F)      /* 1024 */
#define NBLK 512

typedef unsigned long long ull;

// ---------------- scratch (no allocations allowed) ----------------
__device__ float g_projT[ELF * S];            // [e][l][g][s]  raw proj (pre-std-scale)
__device__ float g_red[ELF * SAMPLE];         // red = ksum/len per (row, grid point)
__device__ float g_sp1[NBLK * 32];            // per-tile per-f partial sum
__device__ float g_sp2[NBLK * 32];            // per-tile per-f partial sumsq
__device__ float g_bmin[NBLK], g_bmax[NBLK];
__device__ float g_store[6 * L * F];          // per-pair summed |diff|
__device__ unsigned g_bar1 = 0, g_bar2 = 0, g_bar3 = 0;   // self-resetting

__device__ __forceinline__ float ex2(float x) {
    float y; asm("ex2.approx.ftz.f32 %0, %1;" : "=f"(y) : "f"(x)); return y;
}
// f32x2 packed helpers (Blackwell packed fp32 pipe)
__device__ __forceinline__ ull pk2(float a, float b) {
    ull r; asm("mov.b64 %0, {%1, %2};" : "=l"(r) : "f"(a), "f"(b)); return r;
}
__device__ __forceinline__ void upk2(ull v, float& a, float& b) {
    asm("mov.b64 {%0, %1}, %2;" : "=f"(a), "=f"(b) : "l"(v));
}
__device__ __forceinline__ ull mul2(ull a, ull b) {
    ull r; asm("mul.rn.f32x2 %0, %1, %2;" : "=l"(r) : "l"(a), "l"(b)); return r;
}
__device__ __forceinline__ ull add2(ull a, ull b) {
    ull r; asm("add.rn.f32x2 %0, %1, %2;" : "=l"(r) : "l"(a), "l"(b)); return r;
}
__device__ __forceinline__ ull fma2(ull a, ull b, ull c) {
    ull r; asm("fma.rn.f32x2 %0, %1, %2, %3;" : "=l"(r) : "l"(a), "l"(b), "l"(c)); return r;
}

union __align__(16) Smem {
    struct { float sp[F * F]; float mt[32 * F]; float tr[32 * F];
             float r0[256], r1[256], r2[256], r3[256]; } p1;   // 16 KB
    struct { float su[S]; float part[8][SAMPLE]; } p2;          // 18 KB
    struct { float swarp[6][8]; float sfinal[6]; float str[256], ste[256]; } p3;
};

// device-wide barrier: arrive (release) + wait (acquire)
__device__ __forceinline__ void dev_barrier(unsigned* bar, unsigned target) {
    __syncthreads();
    if (threadIdx.x == 0) {
        __threadfence();
        atomicAdd(bar, 1u);
        while (*(volatile unsigned*)bar < target) __nanosleep(64);
        __threadfence();
    }
    __syncthreads();
}

__global__ void __launch_bounds__(256) k_all(const float* __restrict__ matrix,
                                             const float* __restrict__ params,
                                             const int* __restrict__ data_len,
                                             float* __restrict__ out) {
    __shared__ Smem sm;
    __shared__ float sC[4];
    int b = blockIdx.x;
    int tid = threadIdx.x;
    int g = tid & 31, rg = tid >> 5;

    // ============ PHASE 1: proj tile (32 s-rows x 32 f) + stats ============
    {
        int el = b >> 4, ts = b & 15;
        ((float4*)sm.p1.sp)[tid] = ((const float4*)params)[tid];   // 4 KB
        ((float4*)sm.p1.mt)[tid] =
            ((const float4*)(matrix + ((size_t)el * S + (size_t)ts * 32) * F))[tid]; // 4 KB
        __syncthreads();

        // std partials over this tile's 4 rows per thread (f = g)
        float s1 = 0.f, s2 = 0.f;
        #pragma unroll
        for (int k = 0; k < 4; k++) {
            float x = sm.p1.mt[(rg + k * 8) * F + g];
            s1 += x; s2 += x * x;
        }
        sm.p1.r2[tid] = s1; sm.p1.r3[tid] = s2;

        // GEMM: 4 independent row chains
        float acc[4] = {0.f, 0.f, 0.f, 0.f};
        #pragma unroll
        for (int f = 0; f < F; f++) {
            float pv = sm.p1.sp[f * F + g];
            #pragma unroll
            for (int k = 0; k < 4; k++)
                acc[k] += sm.p1.mt[(rg + k * 8) * F + f] * pv;
        }
        float mn = CUDART_INF_F, mx = -CUDART_INF_F;
        #pragma unroll
        for (int k = 0; k < 4; k++) {
            sm.p1.tr[g * 32 + rg + k * 8] = acc[k];
            mn = fminf(mn, acc[k]); mx = fmaxf(mx, acc[k]);
        }
        sm.p1.r0[tid] = mn; sm.p1.r1[tid] = mx;
        __syncthreads();

        // coalesced transposed store: f = tid>>3, 4 consecutive s
        {
            int gg = tid >> 3, j = tid & 7;
            *(float4*)(g_projT + ((size_t)el * F + gg) * S + (size_t)ts * 32 + j * 4) =
                *(const float4*)(sm.p1.tr + gg * 32 + j * 4);
        }

        for (int st = 128; st; st >>= 1) {
            if (tid < st) {
                sm.p1.r0[tid] = fminf(sm.p1.r0[tid], sm.p1.r0[tid + st]);
                sm.p1.r1[tid] = fmaxf(sm.p1.r1[tid], sm.p1.r1[tid + st]);
                if (st >= 32) { sm.p1.r2[tid] += sm.p1.r2[tid + st];
                                sm.p1.r3[tid] += sm.p1.r3[tid + st]; }
            }
            __syncthreads();
        }
        if (tid < 32) { g_sp1[b * 32 + tid] = sm.p1.r2[tid];
                        g_sp2[b * 32 + tid] = sm.p1.r3[tid]; }
        if (tid == 0) { g_bmin[b] = sm.p1.r0[0]; g_bmax[b] = sm.p1.r1[0]; }
    }

    dev_barrier(&g_bar1, NBLK);

    // ============ CONSTS: every block computes scalars redundantly ============
    float uscale, qleft, h, sc;
    {
        float sdsum = 0.f;
        for (int c = tid; c < ELF; c += 256) {
            int cel = c >> 5, f = c & 31;
            float s1 = 0.f, s2 = 0.f;
            #pragma unroll
            for (int st = 0; st < 16; st++) {
                int idx = ((cel * 16 + st) << 5) + f;
                s1 += g_sp1[idx]; s2 += g_sp2[idx];
            }
            float mean = s1 / (float)S;
            float var = (s2 - s1 * mean) / (float)(S - 1);
            sdsum += sqrtf(fmaxf(var, 0.f));
        }
        sm.p1.r2[tid] = sdsum;
        sm.p1.r0[tid] = fminf(g_bmin[tid], g_bmin[tid + 256]);
        sm.p1.r1[tid] = fmaxf(g_bmax[tid], g_bmax[tid + 256]);
        __syncthreads();
        for (int st = 128; st; st >>= 1) {
            if (tid < st) {
                sm.p1.r2[tid] += sm.p1.r2[tid + st];
                sm.p1.r0[tid] = fminf(sm.p1.r0[tid], sm.p1.r0[tid + st]);
                sm.p1.r1[tid] = fmaxf(sm.p1.r1[tid], sm.p1.r1[tid + st]);
            }
            __syncthreads();
        }
        if (tid == 0) {
            float stdv = sm.p1.r2[0] / (float)ELF;
            // mean(std(matrix/stdv)) == 1 exactly (positive homogeneity)
            float bw = 1.06f * powf((float)S, -0.2f);
            float left = sm.p1.r0[0] / stdv, right = sm.p1.r1[0] / stdv;
            float range = right - left;
            float delta = range / (float)SAMPLE;
            float gstep = range / (float)(SAMPLE - 1);
            float coef = (0.5f / (bw * bw)) * 1.4426950408889634f;  // fold log2(e)
            float sa = sqrtf(coef);
            float divisor = sqrtf(2.f * CUDART_PI_F) * bw;
            sC[0] = sa / stdv;           // uscale
            sC[1] = left * sa;           // qleft (scaled)
            sC[2] = gstep * sa;          // qstep h (scaled)
            sC[3] = delta / (2.f * divisor);  // final per-pair scale
        }
        __syncthreads();
        uscale = sC[0]; qleft = sC[1]; h = sC[2]; sc = sC[3];
    }

    // ============ PHASE 2: KDE via factored geometric recurrence (EXACT) ============
    // K(u,p) = 2^{-(t0 - dp h)^2} = c * g^dp * W_dp; W_dp sample-independent.
    // Masked-tail identity: (ksum - corr)/len == sum_{s<len} K/len.
    {
        int warp = rg, lane = g;
        float twoh = 2.0f * h;
        float qb = qleft + (float)(lane << 4) * h;  // 16 contiguous points per lane
        float m2hqb = -twoh * qb;
        #pragma unroll 1
        for (int rr = 0; rr < 2; rr++) {
            int elf = (b << 1) | rr;
            int el2 = elf >> 5;
            int len = data_len[el2];
            const float* src = g_projT + (size_t)elf * S;
            __syncthreads();                        // protect su reuse across rows
            for (int s = tid; s < len; s += 256) sm.p2.su[s] = src[s] * uscale;
            __syncthreads();

            int eighth = (len + 7) >> 3;
            int sBeg = warp * eighth;
            int sEnd = min(sBeg + eighth, len);

            ull a0, a1, a2, a3, a4, a5, a6, a7;
            a0 = a1 = a2 = a3 = a4 = a5 = a6 = a7 = pk2(0.f, 0.f);
            #pragma unroll 2
            for (int s = sBeg; s < sEnd; s++) {
                float u = sm.p2.su[s];
                float t0 = u - qb;
                float c = ex2(__fmul_rn(t0, -t0));
                float gv = ex2(fmaf(u, twoh, m2hqb));
                float g2 = gv * gv;
                float g4 = g2 * g2;
                float g8 = g4 * g4;
                ull gg = pk2(g2, g2);
                ull G8 = pk2(g8, g8);
                ull tA = pk2(c, c * gv);            // points (0,1)
                a4 = fma2(tA, G8, a4); a0 = add2(a0, tA); tA = mul2(tA, gg);
                a5 = fma2(tA, G8, a5); a1 = add2(a1, tA); tA = mul2(tA, gg);
                a6 = fma2(tA, G8, a6); a2 = add2(a2, tA); tA = mul2(tA, gg);
                a7 = fma2(tA, G8, a7); a3 = add2(a3, tA);
            }

            float* pw = sm.p2.part[warp] + (lane << 4);
            upk2(a0, pw[0],  pw[1]);   upk2(a1, pw[2],  pw[3]);
            upk2(a2, pw[4],  pw[5]);   upk2(a3, pw[6],  pw[7]);
            upk2(a4, pw[8],  pw[9]);   upk2(a5, pw[10], pw[11]);
            upk2(a6, pw[12], pw[13]);  upk2(a7, pw[14], pw[15]);
            __syncthreads();

            float invlen = 1.0f / (float)len;
            int pt0 = tid << 1;
            float tmp[2];
            #pragma unroll
            for (int i = 0; i < 2; i++) {
                int pt = pt0 + i;
                float ssumv = ((sm.p2.part[0][pt] + sm.p2.part[1][pt])
                             + (sm.p2.part[2][pt] + sm.p2.part[3][pt]))
                            + ((sm.p2.part[4][pt] + sm.p2.part[5][pt])
                             + (sm.p2.part[6][pt] + sm.p2.part[7][pt]));
                float dh = (float)(pt & 15) * h;
                tmp[i] = ssumv * ex2(__fmul_rn(dh, -dh)) * invlen;
            }
            *(float2*)(g_red + (size_t)elf * SAMPLE + pt0) = make_float2(tmp[0], tmp[1]);
        }
    }

    dev_barrier(&g_bar2, NBLK);

    // ============ PHASE 3: pairwise |diff| sums (blocks 0..255) ============
    // pair order (i<j): 0:(0,1) 1:(0,2) 2:(0,3) 3:(1,2) 4:(1,3) 5:(2,3); train={0,1,3}
    if (b < 256) {
        int warp = rg, lane = g;
        float local[6];
        #pragma unroll
        for (int p = 0; p < 6; p++) local[p] = 0.f;
        #pragma unroll
        for (int halfi = 0; halfi < 2; halfi++) {
            int pt = tid + halfi * 256;
            float r[E];
            #pragma unroll
            for (int e = 0; e < E; e++)
                r[e] = g_red[((size_t)(e * 256 + b)) * SAMPLE + pt];
            int p = 0;
            #pragma unroll
            for (int i = 0; i < E; i++)
                #pragma unroll
                for (int j = i + 1; j < E; j++)
                    local[p++] += fabsf(r[i] - r[j]);
        }
        #pragma unroll
        for (int p = 0; p < 6; p++) {
            #pragma unroll
            for (int o = 16; o; o >>= 1)
                local[p] += __shfl_down_sync(0xffffffffu, local[p], o);
        }
        if (lane == 0)
            #pragma unroll
            for (int p = 0; p < 6; p++) sm.p3.swarp[p][warp] = local[p];
        __syncthreads();
        if (warp == 0) {
            #pragma unroll
            for (int p = 0; p < 6; p++) {
                float v = (lane < 8) ? sm.p3.swarp[p][lane] : 0.f;
                #pragma unroll
                for (int o = 4; o; o >>= 1)
                    v += __shfl_down_sync(0xffffffffu, v, o);
                if (lane == 0) sm.p3.sfinal[p] = v;
            }
            __syncwarp();
            if (lane < 6) g_store[lane * 256 + b] = sm.p3.sfinal[lane];
        }
    }

    // arrive at final barrier; only block NBLK-1 continues to emit output
    __syncthreads();
    if (tid == 0) { __threadfence(); atomicAdd(&g_bar3, 1u); }
    if (b != NBLK - 1) return;
    if (tid == 0) {
        while (*(volatile unsigned*)&g_bar3 < NBLK) __nanosleep(64);
        __threadfence();
        g_bar1 = 0; g_bar2 = 0;          // safe: bar3 full => nobody spins on bar1/bar2
    }
    __syncthreads();

    // ============ OUTPUT (block NBLK-1) ============
    {
        float s0 = g_store[0 * 256 + tid], s1 = g_store[1 * 256 + tid];
        float s2 = g_store[2 * 256 + tid], s3 = g_store[3 * 256 + tid];
        float s4 = g_store[4 * 256 + tid], s5 = g_store[5 * 256 + tid];
        float te = fmaxf(fmaxf(fmaxf(s0, s1), fmaxf(s2, s3)), fmaxf(s4, s5)) * sc;
        float tr = fmaxf(fmaxf(s0, s1), s3) * sc;
        out[tid] = tr;          // train_results (L,F)
        out[256 + tid] = te;    // test_results  (L,F)
        sm.p3.str[tid] = tr; sm.p3.ste[tid] = te;
        __syncthreads();
        if (tid < 32) {
            float mtr = -CUDART_INF_F, mte = -CUDART_INF_F;
            #pragma unroll
            for (int l = 0; l < L; l++) {
                mtr = fmaxf(mtr, sm.p3.str[l * 32 + tid]);
                mte = fmaxf(mte, sm.p3.ste[l * 32 + tid]);
            }
            #pragma unroll
            for (int o = 16; o; o >>= 1) {
                mtr += __shfl_down_sync(0xffffffffu, mtr, o);
                mte += __shfl_down_sync(0xffffffffu, mte, o);
            }
            if (tid == 0) {
                out[512] = mtr / 32.f;
                out[513] = mte / 32.f;
                g_bar3 = 0;              // sole reader; safe to reset last
            }
        }
    }
}

extern "C" void kernel_launch(void* const* d_in, const int* in_sizes, int n_in,
                              void* d_out, int out_size) {
    const float* matrix   = (const float*)d_in[0];   // (E,L,S,F) f32
    const float* params   = (const float*)d_in[1];   // (F,F) f32
    const int*   data_len = (const int*)d_in[2];     // (E,L) i32
    float* out = (float*)d_out;                      // 514 f32

    k_all<<<NBLK, 256>>>(matrix, params, data_len, out);
}